// round 1
// baseline (speedup 1.0000x reference)
#include <cuda_runtime.h>
#include <math.h>

#define NN 50000
#define NE 800000
#define C1 128   // hidden channels
#define C2 64    // output channels
#define K1 128   // layer1 K
#define K2 128   // layer2 K

// ---------------- scratch (static device globals — allocation-free) --------
__device__ float g_h1[(size_t)NN * C1];    // x @ W1
__device__ float g_agg1[(size_t)NN * C1];  // aggregated + relu(h1)
__device__ float g_h2[(size_t)NN * C2];    // h1r @ W2
__device__ float g_deg[NN];
__device__ float g_dinv[NN];

// ---------------- vector reduction (sm_90+: red.global.add.v4.f32) ---------
__device__ __forceinline__ void red_add_v4(float4* p, float a, float b, float c, float d) {
    asm volatile("red.global.add.v4.f32 [%0], {%1, %2, %3, %4};"
                 :: "l"(p), "f"(a), "f"(b), "f"(c), "f"(d) : "memory");
}

// ---------------- degree / norm ---------------------------------------------
__global__ void k_init_deg(float* deg, int n) {
    int i = blockIdx.x * blockDim.x + threadIdx.x;
    if (i < n) deg[i] = 1.0f;  // self-loop
}

__global__ void k_count(const int* __restrict__ col, float* deg, int e) {
    int i = blockIdx.x * blockDim.x + threadIdx.x;
    if (i < e) atomicAdd(&deg[col[i]], 1.0f);
}

__global__ void k_dinv(const float* __restrict__ deg, float* dinv, int n) {
    int i = blockIdx.x * blockDim.x + threadIdx.x;
    if (i < n) dinv[i] = rsqrtf(deg[i]);  // deg >= 1 always (self-loop)
}

// ---------------- dense transform: H = X @ W  (warp per row, W in smem) -----
// W row-major [K, C]. Each warp computes one output row; x row held in regs,
// broadcast via shfl; W read from shared.
template <int K, int C>
__global__ void k_gemm(const float* __restrict__ X, const float* __restrict__ W,
                       float* __restrict__ H, int n) {
    extern __shared__ float Ws[];  // K*C floats
    for (int i = threadIdx.x; i < K * C; i += blockDim.x) Ws[i] = W[i];
    __syncthreads();

    int warp = (blockIdx.x * blockDim.x + threadIdx.x) >> 5;
    int lane = threadIdx.x & 31;
    if (warp >= n) return;

    const float* xr = X + (size_t)warp * K;
    float xreg[K / 32];
#pragma unroll
    for (int i = 0; i < K / 32; i++) xreg[i] = xr[i * 32 + lane];

    float acc[C / 32];
#pragma unroll
    for (int i = 0; i < C / 32; i++) acc[i] = 0.0f;

#pragma unroll
    for (int k = 0; k < K; k++) {
        float xk = __shfl_sync(0xffffffffu, xreg[k >> 5], k & 31);
#pragma unroll
        for (int c = 0; c < C / 32; c++)
            acc[c] = fmaf(xk, Ws[k * C + c * 32 + lane], acc[c]);
    }

    float* hr = H + (size_t)warp * C;
#pragma unroll
    for (int c = 0; c < C / 32; c++) hr[c * 32 + lane] = acc[c];
}

// ---------------- self-loop init: AGG[i] = dinv[i]^2 * H[i] -----------------
template <int C>
__global__ void k_selfloop(const float* __restrict__ H, const float* __restrict__ dinv,
                           float* __restrict__ AGG, int n) {
    constexpr int V = C / 4;
    int idx = blockIdx.x * blockDim.x + threadIdx.x;
    if (idx >= n * V) return;
    int node = idx / V;
    int l    = idx % V;
    float di = dinv[node];
    float w  = di * di;
    float4 v = reinterpret_cast<const float4*>(H + (size_t)node * C)[l];
    reinterpret_cast<float4*>(AGG + (size_t)node * C)[l] =
        make_float4(w * v.x, w * v.y, w * v.z, w * v.w);
}

// ---------------- edge scatter: AGG[col] += norm * H[row] -------------------
template <int C>
__global__ void k_scatter(const float* __restrict__ H, const int* __restrict__ rows,
                          const int* __restrict__ cols, const float* __restrict__ dinv,
                          float* __restrict__ AGG, int e) {
    constexpr int LPE = C / 4;  // lanes per edge (32 for C=128, 16 for C=64)
    int gid = blockIdx.x * blockDim.x + threadIdx.x;
    int edge = gid / LPE;
    int l    = gid % LPE;
    if (edge >= e) return;
    int r = rows[edge];
    int c = cols[edge];
    float nrm = dinv[r] * dinv[c];
    float4 v = __ldg(reinterpret_cast<const float4*>(H + (size_t)r * C) + l);
    red_add_v4(reinterpret_cast<float4*>(AGG + (size_t)c * C) + l,
               nrm * v.x, nrm * v.y, nrm * v.z, nrm * v.w);
}

// ---------------- bias (+ optional relu), in-place --------------------------
template <int C, bool RELU>
__global__ void k_bias(float* __restrict__ A, const float* __restrict__ b, int n) {
    int idx = blockIdx.x * blockDim.x + threadIdx.x;
    if (idx >= n * C) return;
    int c = idx & (C - 1);
    float v = A[idx] + b[c];
    if (RELU) v = fmaxf(v, 0.0f);
    A[idx] = v;
}

// ---------------- launch -----------------------------------------------------
extern "C" void kernel_launch(void* const* d_in, const int* in_sizes, int n_in,
                              void* d_out, int out_size) {
    const float* x  = (const float*)d_in[0];
    const int*   ei = (const int*)d_in[1];   // [2, NE] : rows = ei, cols = ei + NE
    const float* W1 = (const float*)d_in[2];
    const float* b1 = (const float*)d_in[3];
    const float* W2 = (const float*)d_in[4];
    const float* b2 = (const float*)d_in[5];
    float* out = (float*)d_out;

    const int* rows = ei;
    const int* cols = ei + NE;

    float *h1, *agg1, *h2, *deg, *dinv;
    cudaGetSymbolAddress((void**)&h1,   g_h1);
    cudaGetSymbolAddress((void**)&agg1, g_agg1);
    cudaGetSymbolAddress((void**)&h2,   g_h2);
    cudaGetSymbolAddress((void**)&deg,  g_deg);
    cudaGetSymbolAddress((void**)&dinv, g_dinv);

    const int T = 256;

    // degree / normalization
    k_init_deg<<<(NN + T - 1) / T, T>>>(deg, NN);
    k_count<<<(NE + T - 1) / T, T>>>(cols, deg, NE);
    k_dinv<<<(NN + T - 1) / T, T>>>(deg, dinv, NN);

    // layer 1: transform
    static bool attr_set = false;
    cudaFuncSetAttribute(k_gemm<K1, C1>, cudaFuncAttributeMaxDynamicSharedMemorySize,
                         K1 * C1 * (int)sizeof(float));
    (void)attr_set;
    {
        int warps = NN;
        int blocks = (warps * 32 + T - 1) / T;
        k_gemm<K1, C1><<<blocks, T, K1 * C1 * sizeof(float)>>>(x, W1, h1, NN);
    }
    // layer 1: aggregate (self-loop init + edge scatter), bias + relu
    k_selfloop<C1><<<((NN * (C1 / 4)) + T - 1) / T, T>>>(h1, dinv, agg1, NN);
    {
        long long total = (long long)NE * (C1 / 4);
        int blocks = (int)((total + T - 1) / T);
        k_scatter<C1><<<blocks, T>>>(h1, rows, cols, dinv, agg1, NE);
    }
    k_bias<C1, true><<<((NN * C1) + T - 1) / T, T>>>(agg1, b1, NN);

    // layer 2: transform
    {
        int warps = NN;
        int blocks = (warps * 32 + T - 1) / T;
        k_gemm<K2, C2><<<blocks, T, K2 * C2 * sizeof(float)>>>(agg1, W2, h2, NN);
    }
    // layer 2: aggregate into d_out, then bias
    k_selfloop<C2><<<((NN * (C2 / 4)) + T - 1) / T, T>>>(h2, dinv, out, NN);
    {
        long long total = (long long)NE * (C2 / 4);
        int blocks = (int)((total + T - 1) / T);
        k_scatter<C2><<<blocks, T>>>(h2, rows, cols, dinv, out, NE);
    }
    k_bias<C2, false><<<((NN * C2) + T - 1) / T, T>>>(out, b2, NN);
}

// round 2
// speedup vs baseline: 1.5811x; 1.5811x over previous
#include <cuda_runtime.h>
#include <math.h>

#define NN 50000
#define NE 800000
#define C1 128   // hidden channels
#define C2 64    // output channels

// ---------------- scratch (static device globals — allocation-free) --------
__device__ float g_h1[(size_t)NN * C1];    // x @ W1
__device__ float g_agg1[(size_t)NN * C1];  // aggregated + relu(h1)
__device__ float g_h2[(size_t)NN * C2];    // h1r @ W2
__device__ float g_deg[NN];
__device__ float g_dinv[NN];

// ---------------- vector reduction (sm_90+: red.global.add.v4.f32) ---------
__device__ __forceinline__ void red_add_v4(float4* p, float a, float b, float c, float d) {
    asm volatile("red.global.add.v4.f32 [%0], {%1, %2, %3, %4};"
                 :: "l"(p), "f"(a), "f"(b), "f"(c), "f"(d) : "memory");
}

// ---------------- degree / norm ---------------------------------------------
__global__ void k_init_deg(float* deg, int n) {
    int i = blockIdx.x * blockDim.x + threadIdx.x;
    if (i < n) deg[i] = 1.0f;  // self-loop
}

__global__ void k_count(const int* __restrict__ col, float* deg, int e) {
    int i = blockIdx.x * blockDim.x + threadIdx.x;
    if (i < e) atomicAdd(&deg[col[i]], 1.0f);
}

__global__ void k_dinv(const float* __restrict__ deg, float* dinv, int n) {
    int i = blockIdx.x * blockDim.x + threadIdx.x;
    if (i < n) dinv[i] = rsqrtf(deg[i]);  // deg >= 1 always (self-loop)
}

// ---------------- fused dense transform + self-loop init --------------------
// H[N, C] = X[N, 128] @ W[128, C];  AGG[i] = dinv[i]^2 * H[i]
// Register-blocked tiling: BM=128 rows, BK=16, 256 threads, thread tile 8 x (C/16).
template <int C>
__global__ __launch_bounds__(256)
void k_gemm_fused(const float* __restrict__ X, const float* __restrict__ W,
                  const float* __restrict__ dinv,
                  float* __restrict__ H, float* __restrict__ AGG, int n) {
    constexpr int K  = 128;
    constexpr int BM = 128;
    constexpr int BK = 16;
    constexpr int TM = 8;
    constexpr int TN = C / 16;  // 8 for C=128, 4 for C=64

    extern __shared__ float sm[];
    float* Ws = sm;            // [K][C]
    float* As = sm + K * C;    // [BK][BM] (transposed X tile)

    const int tid  = threadIdx.x;
    const int row0 = blockIdx.x * BM;
    const int tr   = tid >> 4;          // 0..15
    const int tc   = tid & 15;          // 0..15

    // load full W into shared (once)
    for (int i = tid; i < K * C / 4; i += 256)
        reinterpret_cast<float4*>(Ws)[i] = reinterpret_cast<const float4*>(W)[i];

    float acc[TM][TN];
#pragma unroll
    for (int i = 0; i < TM; i++)
#pragma unroll
        for (int j = 0; j < TN; j++) acc[i][j] = 0.0f;

    for (int k0 = 0; k0 < K; k0 += BK) {
        __syncthreads();  // W ready (first iter) / prev As consumed
        // stage X[row0 : row0+128][k0 : k0+16] into As transposed (As[kk][row])
#pragma unroll
        for (int l = 0; l < 2; l++) {
            int idx = tid + l * 256;   // 0..511
            int r   = idx >> 2;        // 0..127
            int v   = idx & 3;         // which float4 of the 16 k's
            float4 xv = make_float4(0.f, 0.f, 0.f, 0.f);
            if (row0 + r < n)
                xv = reinterpret_cast<const float4*>(X + (size_t)(row0 + r) * K + k0)[v];
            As[(v * 4 + 0) * BM + r] = xv.x;
            As[(v * 4 + 1) * BM + r] = xv.y;
            As[(v * 4 + 2) * BM + r] = xv.z;
            As[(v * 4 + 3) * BM + r] = xv.w;
        }
        __syncthreads();

#pragma unroll
        for (int kk = 0; kk < BK; kk++) {
            float a[TM], b[TN];
            const float4* ap = reinterpret_cast<const float4*>(As + kk * BM + tr * TM);
            float4 a0 = ap[0], a1 = ap[1];
            a[0]=a0.x; a[1]=a0.y; a[2]=a0.z; a[3]=a0.w;
            a[4]=a1.x; a[5]=a1.y; a[6]=a1.z; a[7]=a1.w;
            const float4* bp = reinterpret_cast<const float4*>(Ws + (k0 + kk) * C + tc * TN);
            float4 b0 = bp[0];
            b[0]=b0.x; b[1]=b0.y; b[2]=b0.z; b[3]=b0.w;
            if (TN == 8) {
                float4 b1 = bp[1];
                b[4]=b1.x; b[5]=b1.y; b[6]=b1.z; b[7]=b1.w;
            }
#pragma unroll
            for (int i = 0; i < TM; i++)
#pragma unroll
                for (int j = 0; j < TN; j++)
                    acc[i][j] = fmaf(a[i], b[j], acc[i][j]);
        }
    }

    // epilogue: H = acc, AGG = dinv^2 * acc
#pragma unroll
    for (int i = 0; i < TM; i++) {
        int row = row0 + tr * TM + i;
        if (row >= n) break;
        float di = dinv[row];
        float w  = di * di;
        float* hr = H   + (size_t)row * C + tc * TN;
        float* ar = AGG + (size_t)row * C + tc * TN;
#pragma unroll
        for (int j = 0; j < TN; j += 4) {
            float4 hv = make_float4(acc[i][j], acc[i][j+1], acc[i][j+2], acc[i][j+3]);
            reinterpret_cast<float4*>(hr)[j / 4] = hv;
            reinterpret_cast<float4*>(ar)[j / 4] =
                make_float4(w * hv.x, w * hv.y, w * hv.z, w * hv.w);
        }
    }
}

// ---------------- edge scatter: AGG[col] += norm * H[row] -------------------
template <int C>
__global__ void k_scatter(const float* __restrict__ H, const int* __restrict__ rows,
                          const int* __restrict__ cols, const float* __restrict__ dinv,
                          float* __restrict__ AGG, int e) {
    constexpr int LPE = C / 4;  // lanes per edge
    int gid = blockIdx.x * blockDim.x + threadIdx.x;
    int edge = gid / LPE;
    int l    = gid % LPE;
    if (edge >= e) return;
    int r = rows[edge];
    int c = cols[edge];
    float nrm = dinv[r] * dinv[c];
    float4 v = __ldg(reinterpret_cast<const float4*>(H + (size_t)r * C) + l);
    red_add_v4(reinterpret_cast<float4*>(AGG + (size_t)c * C) + l,
               nrm * v.x, nrm * v.y, nrm * v.z, nrm * v.w);
}

// ---------------- bias (+ optional relu), in-place --------------------------
template <int C, bool RELU>
__global__ void k_bias(float* __restrict__ A, const float* __restrict__ b, int n) {
    int idx = blockIdx.x * blockDim.x + threadIdx.x;
    if (idx >= n * C) return;
    int c = idx & (C - 1);
    float v = A[idx] + b[c];
    if (RELU) v = fmaxf(v, 0.0f);
    A[idx] = v;
}

// ---------------- launch -----------------------------------------------------
extern "C" void kernel_launch(void* const* d_in, const int* in_sizes, int n_in,
                              void* d_out, int out_size) {
    const float* x  = (const float*)d_in[0];
    const int*   ei = (const int*)d_in[1];   // [2, NE] : rows = ei, cols = ei + NE
    const float* W1 = (const float*)d_in[2];
    const float* b1 = (const float*)d_in[3];
    const float* W2 = (const float*)d_in[4];
    const float* b2 = (const float*)d_in[5];
    float* out = (float*)d_out;

    const int* rows = ei;
    const int* cols = ei + NE;

    float *h1, *agg1, *h2, *deg, *dinv;
    cudaGetSymbolAddress((void**)&h1,   g_h1);
    cudaGetSymbolAddress((void**)&agg1, g_agg1);
    cudaGetSymbolAddress((void**)&h2,   g_h2);
    cudaGetSymbolAddress((void**)&deg,  g_deg);
    cudaGetSymbolAddress((void**)&dinv, g_dinv);

    const int T = 256;
    const int SMEM1 = (128 * C1 + 16 * 128) * (int)sizeof(float);  // 73728
    const int SMEM2 = (128 * C2 + 16 * 128) * (int)sizeof(float);  // 40960

    cudaFuncSetAttribute(k_gemm_fused<C1>, cudaFuncAttributeMaxDynamicSharedMemorySize, SMEM1);
    cudaFuncSetAttribute(k_gemm_fused<C2>, cudaFuncAttributeMaxDynamicSharedMemorySize, SMEM2);

    // degree / normalization
    k_init_deg<<<(NN + T - 1) / T, T>>>(deg, NN);
    k_count<<<(NE + T - 1) / T, T>>>(cols, deg, NE);
    k_dinv<<<(NN + T - 1) / T, T>>>(deg, dinv, NN);

    const int GB = (NN + 127) / 128;  // 391

    // layer 1: transform + self-loop init fused
    k_gemm_fused<C1><<<GB, T, SMEM1>>>(x, W1, dinv, h1, agg1, NN);
    // layer 1: edge scatter, then bias + relu
    {
        long long total = (long long)NE * (C1 / 4);
        int blocks = (int)((total + T - 1) / T);
        k_scatter<C1><<<blocks, T>>>(h1, rows, cols, dinv, agg1, NE);
    }
    k_bias<C1, true><<<((NN * C1) + T - 1) / T, T>>>(agg1, b1, NN);

    // layer 2: transform + self-loop init fused (AGG -> d_out)
    k_gemm_fused<C2><<<GB, T, SMEM2>>>(agg1, W2, dinv, h2, out, NN);
    // layer 2: edge scatter into d_out, then bias
    {
        long long total = (long long)NE * (C2 / 4);
        int blocks = (int)((total + T - 1) / T);
        k_scatter<C2><<<blocks, T>>>(h2, rows, cols, dinv, out, NE);
    }
    k_bias<C2, false><<<((NN * C2) + T - 1) / T, T>>>(out, b2, NN);
}

// round 3
// speedup vs baseline: 2.5503x; 1.6130x over previous
#include <cuda_runtime.h>
#include <math.h>

#define NN 50000
#define NE 800000
#define C1 128
#define C2 64
#define NBLK ((NN + 255) / 256)   // 196 scan blocks

// ---------------- scratch (static device globals — allocation-free) --------
__device__ float g_h1[(size_t)NN * C1];    // dinv*(x@W1)
__device__ float g_agg1[(size_t)NN * C1];  // layer1 output (post relu)
__device__ float g_h2[(size_t)NN * C2];    // dinv*(agg1@W2)
__device__ float g_dinv[NN];
__device__ int   g_cnt[NN];
__device__ int   g_rowstart[NN + 1];
__device__ int   g_cursor[NN];
__device__ int   g_src[NE];
__device__ int   g_bsum[NBLK];
__device__ int   g_boff[NBLK];

// ---------------- CSR construction ------------------------------------------
__global__ void k_zero(int* cnt, int n) {
    int i = blockIdx.x * blockDim.x + threadIdx.x;
    if (i < n) cnt[i] = 0;
}

__global__ void k_hist(const int* __restrict__ col, int* cnt, int e) {
    int i = blockIdx.x * blockDim.x + threadIdx.x;
    if (i < e) atomicAdd(&cnt[col[i]], 1);
}

// per-block exclusive scan (256 elems) + block totals
__global__ void k_scan_block(const int* __restrict__ cnt, int* ex, int* bsum, int n) {
    __shared__ int sh[256];
    int i = blockIdx.x * 256 + threadIdx.x;
    int v = (i < n) ? cnt[i] : 0;
    sh[threadIdx.x] = v;
    __syncthreads();
    for (int off = 1; off < 256; off <<= 1) {
        int t = (threadIdx.x >= off) ? sh[threadIdx.x - off] : 0;
        __syncthreads();
        sh[threadIdx.x] += t;
        __syncthreads();
    }
    int inc = sh[threadIdx.x];
    if (i < n) ex[i] = inc - v;          // exclusive within block
    if (threadIdx.x == 255) bsum[blockIdx.x] = inc;
}

// single-block exclusive scan of block totals (NBLK <= 256)
__global__ void k_scan_tot(const int* __restrict__ bsum, int* boff, int nb) {
    __shared__ int sh[256];
    int v = (threadIdx.x < nb) ? bsum[threadIdx.x] : 0;
    sh[threadIdx.x] = v;
    __syncthreads();
    for (int off = 1; off < 256; off <<= 1) {
        int t = (threadIdx.x >= off) ? sh[threadIdx.x - off] : 0;
        __syncthreads();
        sh[threadIdx.x] += t;
        __syncthreads();
    }
    if (threadIdx.x < nb) boff[threadIdx.x] = sh[threadIdx.x] - v;
}

// finalize row_start (+cursor copy) and dinv
__global__ void k_finalize(int* rowstart, int* cursor, const int* __restrict__ boff,
                           const int* __restrict__ cnt, float* dinv, int n, int e) {
    int i = blockIdx.x * blockDim.x + threadIdx.x;
    if (i < n) {
        int rs = rowstart[i] + boff[i >> 8];
        rowstart[i] = rs;
        cursor[i]   = rs;
        dinv[i]     = rsqrtf((float)cnt[i] + 1.0f);  // +1 self-loop
    }
    if (i == 0) rowstart[n] = e;
}

__global__ void k_fill(const int* __restrict__ rows, const int* __restrict__ cols,
                       int* cursor, int* src, int e) {
    int i = blockIdx.x * blockDim.x + threadIdx.x;
    if (i < e) {
        int p = atomicAdd(&cursor[cols[i]], 1);
        src[p] = rows[i];
    }
}

// ---------------- fused dense transform: Hs = dinv_row * (X @ W) ------------
template <int C>
__global__ __launch_bounds__(256)
void k_gemm_fused(const float* __restrict__ X, const float* __restrict__ W,
                  const float* __restrict__ dinv, float* __restrict__ Hs, int n) {
    constexpr int K  = 128;
    constexpr int BM = 128;
    constexpr int BK = 16;
    constexpr int TM = 8;
    constexpr int TN = C / 16;  // 8 for C=128, 4 for C=64

    extern __shared__ float sm[];
    float* Ws = sm;            // [K][C]
    float* As = sm + K * C;    // [BK][BM]

    const int tid  = threadIdx.x;
    const int row0 = blockIdx.x * BM;
    const int tr   = tid >> 4;
    const int tc   = tid & 15;

    for (int i = tid; i < K * C / 4; i += 256)
        reinterpret_cast<float4*>(Ws)[i] = reinterpret_cast<const float4*>(W)[i];

    float acc[TM][TN];
#pragma unroll
    for (int i = 0; i < TM; i++)
#pragma unroll
        for (int j = 0; j < TN; j++) acc[i][j] = 0.0f;

    for (int k0 = 0; k0 < K; k0 += BK) {
        __syncthreads();
#pragma unroll
        for (int l = 0; l < 2; l++) {
            int idx = tid + l * 256;
            int r   = idx >> 2;
            int v   = idx & 3;
            float4 xv = make_float4(0.f, 0.f, 0.f, 0.f);
            if (row0 + r < n)
                xv = reinterpret_cast<const float4*>(X + (size_t)(row0 + r) * K + k0)[v];
            As[(v * 4 + 0) * BM + r] = xv.x;
            As[(v * 4 + 1) * BM + r] = xv.y;
            As[(v * 4 + 2) * BM + r] = xv.z;
            As[(v * 4 + 3) * BM + r] = xv.w;
        }
        __syncthreads();

#pragma unroll
        for (int kk = 0; kk < BK; kk++) {
            float a[TM], b[TN];
            const float4* ap = reinterpret_cast<const float4*>(As + kk * BM + tr * TM);
            float4 a0 = ap[0], a1 = ap[1];
            a[0]=a0.x; a[1]=a0.y; a[2]=a0.z; a[3]=a0.w;
            a[4]=a1.x; a[5]=a1.y; a[6]=a1.z; a[7]=a1.w;
            const float4* bp = reinterpret_cast<const float4*>(Ws + (k0 + kk) * C + tc * TN);
            float4 b0 = bp[0];
            b[0]=b0.x; b[1]=b0.y; b[2]=b0.z; b[3]=b0.w;
            if (TN == 8) {
                float4 b1 = bp[1];
                b[4]=b1.x; b[5]=b1.y; b[6]=b1.z; b[7]=b1.w;
            }
#pragma unroll
            for (int i = 0; i < TM; i++)
#pragma unroll
                for (int j = 0; j < TN; j++)
                    acc[i][j] = fmaf(a[i], b[j], acc[i][j]);
        }
    }

#pragma unroll
    for (int i = 0; i < TM; i++) {
        int row = row0 + tr * TM + i;
        if (row >= n) break;
        float di = dinv[row];
        float* hr = Hs + (size_t)row * C + tc * TN;
#pragma unroll
        for (int j = 0; j < TN; j += 4)
            reinterpret_cast<float4*>(hr)[j / 4] =
                make_float4(di * acc[i][j], di * acc[i][j+1],
                            di * acc[i][j+2], di * acc[i][j+3]);
    }
}

// ---------------- CSR gather: out[c] = act(dinv[c]*(Hs[c] + sum Hs[src]) + b)
// warp per node; C=128 -> float4/lane, C=64 -> float2/lane
template <int C, bool RELU>
__global__ void k_gather(const float* __restrict__ Hs, const int* __restrict__ rowstart,
                         const int* __restrict__ src, const float* __restrict__ dinv,
                         const float* __restrict__ bias, float* __restrict__ out, int n) {
    int warp = (blockIdx.x * blockDim.x + threadIdx.x) >> 5;
    int lane = threadIdx.x & 31;
    if (warp >= n) return;
    const int node = warp;

    if (C == 128) {
        const float4* hp = reinterpret_cast<const float4*>(Hs) + (size_t)node * 32 + lane;
        float4 acc = __ldg(hp);  // self-loop term
        int s = rowstart[node], e = rowstart[node + 1];
        for (int j = s; j < e; j++) {
            int r = __ldg(&src[j]);
            float4 v = __ldg(reinterpret_cast<const float4*>(Hs) + (size_t)r * 32 + lane);
            acc.x += v.x; acc.y += v.y; acc.z += v.z; acc.w += v.w;
        }
        float di = dinv[node];
        float4 bv = __ldg(reinterpret_cast<const float4*>(bias) + lane);
        float4 o = make_float4(fmaf(di, acc.x, bv.x), fmaf(di, acc.y, bv.y),
                               fmaf(di, acc.z, bv.z), fmaf(di, acc.w, bv.w));
        if (RELU) {
            o.x = fmaxf(o.x, 0.f); o.y = fmaxf(o.y, 0.f);
            o.z = fmaxf(o.z, 0.f); o.w = fmaxf(o.w, 0.f);
        }
        reinterpret_cast<float4*>(out)[(size_t)node * 32 + lane] = o;
    } else {
        const float2* hp = reinterpret_cast<const float2*>(Hs) + (size_t)node * 32 + lane;
        float2 acc = __ldg(hp);
        int s = rowstart[node], e = rowstart[node + 1];
        for (int j = s; j < e; j++) {
            int r = __ldg(&src[j]);
            float2 v = __ldg(reinterpret_cast<const float2*>(Hs) + (size_t)r * 32 + lane);
            acc.x += v.x; acc.y += v.y;
        }
        float di = dinv[node];
        float2 bv = __ldg(reinterpret_cast<const float2*>(bias) + lane);
        float2 o = make_float2(fmaf(di, acc.x, bv.x), fmaf(di, acc.y, bv.y));
        if (RELU) { o.x = fmaxf(o.x, 0.f); o.y = fmaxf(o.y, 0.f); }
        reinterpret_cast<float2*>(out)[(size_t)node * 32 + lane] = o;
    }
}

// ---------------- launch -----------------------------------------------------
extern "C" void kernel_launch(void* const* d_in, const int* in_sizes, int n_in,
                              void* d_out, int out_size) {
    const float* x  = (const float*)d_in[0];
    const int*   ei = (const int*)d_in[1];   // rows = ei, cols = ei + NE
    const float* W1 = (const float*)d_in[2];
    const float* b1 = (const float*)d_in[3];
    const float* W2 = (const float*)d_in[4];
    const float* b2 = (const float*)d_in[5];
    float* out = (float*)d_out;

    const int* rows = ei;
    const int* cols = ei + NE;

    float *h1, *agg1, *h2, *dinv;
    int *cnt, *rowstart, *cursor, *srcA, *bsum, *boff;
    cudaGetSymbolAddress((void**)&h1,       g_h1);
    cudaGetSymbolAddress((void**)&agg1,     g_agg1);
    cudaGetSymbolAddress((void**)&h2,       g_h2);
    cudaGetSymbolAddress((void**)&dinv,     g_dinv);
    cudaGetSymbolAddress((void**)&cnt,      g_cnt);
    cudaGetSymbolAddress((void**)&rowstart, g_rowstart);
    cudaGetSymbolAddress((void**)&cursor,   g_cursor);
    cudaGetSymbolAddress((void**)&srcA,     g_src);
    cudaGetSymbolAddress((void**)&bsum,     g_bsum);
    cudaGetSymbolAddress((void**)&boff,     g_boff);

    const int T = 256;
    const int SMEM1 = (128 * C1 + 16 * 128) * (int)sizeof(float);
    const int SMEM2 = (128 * C2 + 16 * 128) * (int)sizeof(float);
    cudaFuncSetAttribute(k_gemm_fused<C1>, cudaFuncAttributeMaxDynamicSharedMemorySize, SMEM1);
    cudaFuncSetAttribute(k_gemm_fused<C2>, cudaFuncAttributeMaxDynamicSharedMemorySize, SMEM2);

    // ---- CSR build ----
    k_zero<<<(NN + T - 1) / T, T>>>(cnt, NN);
    k_hist<<<(NE + T - 1) / T, T>>>(cols, cnt, NE);
    k_scan_block<<<NBLK, 256>>>(cnt, rowstart, bsum, NN);
    k_scan_tot<<<1, 256>>>(bsum, boff, NBLK);
    k_finalize<<<(NN + T - 1) / T, T>>>(rowstart, cursor, boff, cnt, dinv, NN, NE);
    k_fill<<<(NE + T - 1) / T, T>>>(rows, cols, cursor, srcA, NE);

    const int GB = (NN + 127) / 128;          // gemm blocks
    const int GW = (NN * 32 + T - 1) / T;     // gather blocks (warp/node)

    // ---- layer 1 ----
    k_gemm_fused<C1><<<GB, T, SMEM1>>>(x, W1, dinv, h1, NN);
    k_gather<C1, true><<<GW, T>>>(h1, rowstart, srcA, dinv, b1, agg1, NN);

    // ---- layer 2 ----
    k_gemm_fused<C2><<<GB, T, SMEM2>>>(agg1, W2, dinv, h2, NN);
    k_gather<C2, false><<<GW, T>>>(h2, rowstart, srcA, dinv, b2, out, NN);
}